// round 6
// baseline (speedup 1.0000x reference)
#include <cuda_runtime.h>
#include <cuda_bf16.h>
#include <string.h>

// NeuralODEClassifier: B=65536 rows, 63 Euler steps of
// f(y)=tanh(y@W1+b1)@W2+b2, then classifier 2->64->relu->64->relu->3.
//
// 4-lane teams: each team integrates 2 batch rows (packed f32x2); each lane
// handles 16 of the 64 hidden units (j = jj*4 + jsel, interleaved for
// conflict-free LDS), per-step allreduce via shfl_xor butterfly (masks 1,2).
// 147 blocks x 896 thr -> 7 warps/SMSP, MUFU 1792 cyc/step (vs 2048 for
// coarse layouts). Integration inner loop uses scalar FFMA accumulators
// (no repack MOVs); classifier splits k across the team with a bank-padded
// Wc2 layout and packed FFMA2. Predicted ~133K cyc, MUFU-bound.

#define T_STEPS 64
#define H 64
#define THREADS 896
#define KPL 16           // k/j per lane

typedef unsigned long long ull;

__device__ __forceinline__ ull pk2(float a, float b) {
    float2 f = make_float2(a, b);
    ull r; memcpy(&r, &f, 8); return r;
}
__device__ __forceinline__ float2 upk(ull v) {
    float2 f; memcpy(&f, &v, 8); return f;
}
__device__ __forceinline__ ull ffma2(ull a, ull b, ull c) {
    ull d;
    asm("fma.rn.f32x2 %0, %1, %2, %3;" : "=l"(d) : "l"(a), "l"(b), "l"(c));
    return d;
}
__device__ __forceinline__ ull fadd2(ull a, ull b) {
    ull d;
    asm("add.rn.f32x2 %0, %1, %2;" : "=l"(d) : "l"(a), "l"(b));
    return d;
}
__device__ __forceinline__ float tanh_fast(float x) {
    float r;
    asm("tanh.approx.f32 %0, %1;" : "=f"(r) : "f"(x));
    return r;
}
// allreduce a packed f32x2 over the 4-lane team (lanes l^1, l^2)
__device__ __forceinline__ ull team_sum2(ull v) {
    v = fadd2(v, __shfl_xor_sync(0xFFFFFFFFu, v, 1, 32));
    v = fadd2(v, __shfl_xor_sync(0xFFFFFFFFu, v, 2, 32));
    return v;
}
__device__ __forceinline__ float team_sum1(float v) {
    v += __shfl_xor_sync(0xFFFFFFFFu, v, 1, 32);
    v += __shfl_xor_sync(0xFFFFFFFFu, v, 2, 32);
    return v;
}

// Wc2 classifier layout: wc2cls[ksel*(64*16+2) + j*16 + kk], each entry the
// duplicated pair {w,w}. Padding (+2) puts the 4 ksel lanes on disjoint
// bank quads for conflict-free LDS.128. (1026*8 % 16 == 0 keeps alignment.)
#define WC2_STRIDE (H * KPL + 2)

__global__ __launch_bounds__(THREADS, 1)
void node_classifier_kernel(
    const float* __restrict__ y0,
    const float* __restrict__ t,
    const float* __restrict__ W1,  // (2,64)
    const float* __restrict__ b1,  // (64)
    const float* __restrict__ W2,  // (64,2)
    const float* __restrict__ b2,  // (2)
    const float* __restrict__ Wc1, // (2,64)
    const float* __restrict__ bc1, // (64)
    const float* __restrict__ Wc2, // (64,64)
    const float* __restrict__ bc2, // (64)
    const float* __restrict__ Wc3, // (64,3)
    const float* __restrict__ bc3, // (3)
    float* __restrict__ out,       // (B,3)
    int nrows)
{
    // ---- SMEM ----------------------------------------------------------
    __shared__ __align__(16) ulonglong2 wza[H];  // ({W1[0][j]}x2, {W1[1][j]}x2)
    __shared__ __align__(16) ulonglong2 wzb[H];  // ({b1[j]}x2,    (W2[j][0],W2[j][1]))
    __shared__ float dts[T_STEPS - 1];
    __shared__ ull   b2pair;                     // (b2[0], b2[1]) NOT duplicated
    __shared__ __align__(16) ulonglong2 cls1[H]; // ({Wc1[0][j]}x2, {Wc1[1][j]}x2)
    __shared__ ull   bc1d[H];                    // {bc1[j]}x2
    __shared__ __align__(16) ull wc2cls[4 * WC2_STRIDE];  // padded, duplicated
    __shared__ ull   bc2d[H];                    // {bc2[j]}x2
    __shared__ float wc3s[H * 3];
    __shared__ float bc3s[3];

    const int tid = threadIdx.x;
    if (tid < H) {
        float a = W1[tid], b = W1[H + tid], c = b1[tid];
        float d = W2[2 * tid], e = W2[2 * tid + 1];
        wza[tid] = make_ulonglong2(pk2(a, a), pk2(b, b));
        wzb[tid] = make_ulonglong2(pk2(c, c), pk2(d, e));
        float p = Wc1[tid], q = Wc1[H + tid], r = bc1[tid], s = bc2[tid];
        cls1[tid] = make_ulonglong2(pk2(p, p), pk2(q, q));
        bc1d[tid] = pk2(r, r);
        bc2d[tid] = pk2(s, s);
    }
    if (tid < T_STEPS - 1) dts[tid] = t[tid + 1] - t[tid];
    for (int i = tid; i < H * H; i += THREADS) {
        int j = i >> 6, k = i & 63;
        float w = Wc2[i];
        wc2cls[(k & 3) * WC2_STRIDE + j * KPL + (k >> 2)] = pk2(w, w);
    }
    for (int i = tid; i < H * 3; i += THREADS) wc3s[i] = Wc3[i];
    if (tid < 3) bc3s[tid] = bc3[tid];
    if (tid == 0) b2pair = pk2(b2[0], b2[1]);
    __syncthreads();

    // ---- team / row mapping ---------------------------------------------
    const int lane = tid & 31;
    const int jsel = lane & 3;          // j/k subset within team
    const int rowg = lane >> 2;         // 0..7: row-pair within warp
    const int gw = blockIdx.x * (THREADS / 32) + (tid >> 5);
    const int npairs = (nrows + 1) >> 1;
    int p = gw * 8 + rowg;
    if (p >= npairs) p = npairs - 1;    // clamp; surplus teams duplicate work
    const int r0 = 2 * p;
    const int r1 = (2 * p + 1 < nrows) ? 2 * p + 1 : r0;

    float2 ya = reinterpret_cast<const float2*>(y0)[r0];
    float2 yb = reinterpret_cast<const float2*>(y0)[r1];
    ull Y0 = pk2(ya.x, yb.x);   // y[0] of rows (A,B)
    ull Y1 = pk2(ya.y, yb.y);   // y[1] of rows (A,B)
    const ull b2p = b2pair;

    // ---- Euler integration: 16 j's per lane, team allreduce per step ----
    #pragma unroll 1
    for (int s = 0; s < T_STEPS - 1; s++) {
        const float dt = dts[s];
        const ull dtp = pk2(dt, dt);
        // scalar accumulators: no repacking MOVs in the hot loop
        float a0A = 0.f, a1A = 0.f, a0B = 0.f, a1B = 0.f;
        #pragma unroll
        for (int jj = 0; jj < KPL; jj++) {
            const int j = jj * 4 + jsel;   // interleaved: conflict-free LDS
            ulonglong2 wa = wza[j];
            ulonglong2 wb = wzb[j];
            ull z = ffma2(Y1, wa.y, ffma2(Y0, wa.x, wb.x));
            float2 zf = upk(z);
            float2 w2p = upk(wb.y);        // (w20, w21): free register halves
            float tA = tanh_fast(zf.x);
            float tB = tanh_fast(zf.y);
            a0A = fmaf(tA, w2p.x, a0A);
            a1A = fmaf(tA, w2p.y, a1A);
            a0B = fmaf(tB, w2p.x, a0B);
            a1B = fmaf(tB, w2p.y, a1B);
        }
        ull ArA = team_sum2(pk2(a0A, a1A));
        ull ArB = team_sum2(pk2(a0B, a1B));
        float2 fA = upk(fadd2(ArA, b2p));   // (f0A, f1A)
        float2 fB = upk(fadd2(ArB, b2p));   // (f0B, f1B)
        Y0 = ffma2(dtp, pk2(fA.x, fB.x), Y0);
        Y1 = ffma2(dtp, pk2(fA.y, fB.y), Y1);
    }

    // ---- Classifier: k split across team (16 k's per lane) --------------
    ull acc[KPL];
    #pragma unroll
    for (int kk = 0; kk < KPL; kk++) acc[kk] = bc2d[kk * 4 + jsel];

    const ull* wrowbase = &wc2cls[jsel * WC2_STRIDE];
    #pragma unroll 1
    for (int j = 0; j < H; j++) {
        ulonglong2 c1 = cls1[j];
        ull hz = ffma2(Y1, c1.y, ffma2(Y0, c1.x, bc1d[j]));
        float2 hf = upk(hz);
        ull hp = pk2(fmaxf(hf.x, 0.f), fmaxf(hf.y, 0.f));
        const ulonglong2* wrow =
            reinterpret_cast<const ulonglong2*>(wrowbase + j * KPL);
        #pragma unroll
        for (int kq = 0; kq < KPL / 2; kq++) {
            ulonglong2 w2 = wrow[kq];
            acc[2 * kq]     = ffma2(hp, w2.x, acc[2 * kq]);
            acc[2 * kq + 1] = ffma2(hp, w2.y, acc[2 * kq + 1]);
        }
    }

    float oA0 = 0.f, oA1 = 0.f, oA2 = 0.f;
    float oB0 = 0.f, oB1 = 0.f, oB2 = 0.f;
    #pragma unroll
    for (int kk = 0; kk < KPL; kk++) {
        const int k = kk * 4 + jsel;
        float2 a = upk(acc[kk]);
        float rA = fmaxf(a.x, 0.f);
        float rB = fmaxf(a.y, 0.f);
        float w0 = wc3s[k * 3 + 0], w1 = wc3s[k * 3 + 1], w2 = wc3s[k * 3 + 2];
        oA0 = fmaf(rA, w0, oA0);
        oA1 = fmaf(rA, w1, oA1);
        oA2 = fmaf(rA, w2, oA2);
        oB0 = fmaf(rB, w0, oB0);
        oB1 = fmaf(rB, w1, oB1);
        oB2 = fmaf(rB, w2, oB2);
    }
    // team-reduce the 3 logits per row; add bias after reduction
    ull oA01 = team_sum2(pk2(oA0, oA1));
    ull oB01 = team_sum2(pk2(oB0, oB1));
    oA2 = team_sum1(oA2);
    oB2 = team_sum1(oB2);

    if (jsel == 0) {
        float2 a01 = upk(oA01);
        out[r0 * 3 + 0] = a01.x + bc3s[0];
        out[r0 * 3 + 1] = a01.y + bc3s[1];
        out[r0 * 3 + 2] = oA2   + bc3s[2];
        float2 b01 = upk(oB01);
        out[r1 * 3 + 0] = b01.x + bc3s[0];
        out[r1 * 3 + 1] = b01.y + bc3s[1];
        out[r1 * 3 + 2] = oB2   + bc3s[2];
    }
}

extern "C" void kernel_launch(void* const* d_in, const int* in_sizes, int n_in,
                              void* d_out, int out_size) {
    const float* y0  = (const float*)d_in[0];
    const float* t   = (const float*)d_in[1];
    const float* W1  = (const float*)d_in[2];
    const float* b1  = (const float*)d_in[3];
    const float* W2  = (const float*)d_in[4];
    const float* b2  = (const float*)d_in[5];
    const float* Wc1 = (const float*)d_in[6];
    const float* bc1 = (const float*)d_in[7];
    const float* Wc2 = (const float*)d_in[8];
    const float* bc2 = (const float*)d_in[9];
    const float* Wc3 = (const float*)d_in[10];
    const float* bc3 = (const float*)d_in[11];
    float* out = (float*)d_out;

    const int nrows = in_sizes[0] / 2;
    // 16 rows per warp; need ceil(nrows/16) warps; 28 warps per block.
    const int warps = (nrows + 15) / 16;
    const int blocks = (warps + (THREADS / 32) - 1) / (THREADS / 32); // 147 @ B=64K
    node_classifier_kernel<<<blocks, THREADS>>>(
        y0, t, W1, b1, W2, b2, Wc1, bc1, Wc2, bc2, Wc3, bc3, out, nrows);
}

// round 7
// speedup vs baseline: 2.0007x; 2.0007x over previous
#include <cuda_runtime.h>
#include <cuda_bf16.h>
#include <string.h>

// NeuralODEClassifier: B=65536 rows, 63 Euler steps of
// f(y)=tanh(y@W1+b1)@W2+b2, then classifier 2->64->relu->64->relu->3.
//
// R6 lesson (ncu): SMEM crossbar was the bottleneck (L1=90.9%) — LDS.128 is
// 4 wavefronts/instr regardless of broadcast. This version keeps ALL ODE
// weights in REGISTERS: 16-lane teams, 4 j's per lane, 5 duplicated {w,w}
// pairs per j (40 regs). Hot loop has zero LDS. Per-step team allreduce via
// 4-level shfl_xor butterfly. MUFU now binds: 1792 cyc/step @ 7 warps/SMSP.

#define T_STEPS 64
#define H 64
#define THREADS 896
#define JPL 4            // j's (and k's) per lane

typedef unsigned long long ull;

__device__ __forceinline__ ull pk2(float a, float b) {
    float2 f = make_float2(a, b);
    ull r; memcpy(&r, &f, 8); return r;
}
__device__ __forceinline__ float2 upk(ull v) {
    float2 f; memcpy(&f, &v, 8); return f;
}
__device__ __forceinline__ ull ffma2(ull a, ull b, ull c) {
    ull d;
    asm("fma.rn.f32x2 %0, %1, %2, %3;" : "=l"(d) : "l"(a), "l"(b), "l"(c));
    return d;
}
__device__ __forceinline__ ull fadd2(ull a, ull b) {
    ull d;
    asm("add.rn.f32x2 %0, %1, %2;" : "=l"(d) : "l"(a), "l"(b));
    return d;
}
__device__ __forceinline__ float tanh_fast(float x) {
    float r;
    asm("tanh.approx.f32 %0, %1;" : "=f"(r) : "f"(x));
    return r;
}
// allreduce a packed f32x2 over a 16-lane team (xor bits 0..3)
__device__ __forceinline__ ull team_sum2(ull v) {
    v = fadd2(v, __shfl_xor_sync(0xFFFFFFFFu, v, 1, 32));
    v = fadd2(v, __shfl_xor_sync(0xFFFFFFFFu, v, 2, 32));
    v = fadd2(v, __shfl_xor_sync(0xFFFFFFFFu, v, 4, 32));
    v = fadd2(v, __shfl_xor_sync(0xFFFFFFFFu, v, 8, 32));
    return v;
}

__global__ __launch_bounds__(THREADS, 1)
void node_classifier_kernel(
    const float* __restrict__ y0,
    const float* __restrict__ t,
    const float* __restrict__ W1,  // (2,64)
    const float* __restrict__ b1,  // (64)
    const float* __restrict__ W2,  // (64,2)
    const float* __restrict__ b2,  // (2)
    const float* __restrict__ Wc1, // (2,64)
    const float* __restrict__ bc1, // (64)
    const float* __restrict__ Wc2, // (64,64)
    const float* __restrict__ bc2, // (64)
    const float* __restrict__ Wc3, // (64,3)
    const float* __restrict__ bc3, // (3)
    float* __restrict__ out,       // (B,3)
    int nrows)
{
    // ---- SMEM (classifier-only + dts; NOT touched in the step loop) -----
    __shared__ float dts[T_STEPS - 1];
    __shared__ __align__(16) ulonglong2 cls1[H];   // ({Wc1[0][j]}x2, {Wc1[1][j]}x2)
    __shared__ ull bc1d[H];                        // {bc1[j]}x2
    // wc2A[(j*16+ksel)*2 + h]: h=0 -> {Wc2[j][ksel]}x2, h=1 -> {Wc2[j][ksel+16]}x2
    // wc2B: same for ksel+32 / ksel+48
    __shared__ __align__(16) ull wc2A[H * 16 * 2];
    __shared__ __align__(16) ull wc2B[H * 16 * 2];
    __shared__ ull bc2d[H];                        // {bc2[k]}x2
    __shared__ ull wc3d[H * 3];                    // {Wc3[k][c]}x2
    __shared__ float bc3s[3];

    const int tid = threadIdx.x;
    if (tid < H) {
        float p = Wc1[tid], q = Wc1[H + tid], r = bc1[tid], s = bc2[tid];
        cls1[tid] = make_ulonglong2(pk2(p, p), pk2(q, q));
        bc1d[tid] = pk2(r, r);
        bc2d[tid] = pk2(s, s);
    }
    if (tid < T_STEPS - 1) dts[tid] = t[tid + 1] - t[tid];
    for (int i = tid; i < H * H; i += THREADS) {
        int j = i >> 6, k = i & 63;
        int ksel = k & 15, kk = k >> 4;
        ull p = pk2(Wc2[i], Wc2[i]);
        int base = (j * 16 + ksel) * 2;
        if (kk == 0)      wc2A[base]     = p;
        else if (kk == 1) wc2A[base + 1] = p;
        else if (kk == 2) wc2B[base]     = p;
        else              wc2B[base + 1] = p;
    }
    for (int i = tid; i < H * 3; i += THREADS) {
        float w = Wc3[i];
        wc3d[i] = pk2(w, w);
    }
    if (tid < 3) bc3s[tid] = bc3[tid];
    __syncthreads();

    // ---- team / row mapping ---------------------------------------------
    const int lane = tid & 31;
    const int jsel = lane & 15;         // j/k subset within 16-lane team
    const int rowg = lane >> 4;         // 0..1: row-pair within warp
    const int gw = blockIdx.x * (THREADS / 32) + (tid >> 5);
    const int npairs = (nrows + 1) >> 1;
    int p = gw * 2 + rowg;
    if (p >= npairs) p = npairs - 1;    // clamp; surplus teams duplicate work
    const int r0 = 2 * p;
    const int r1 = (2 * p + 1 < nrows) ? 2 * p + 1 : r0;

    // ---- ODE weights for this lane's 4 j's -> duplicated register pairs -
    ull w1ad[JPL], w1bd[JPL], b1d[JPL], w20d[JPL], w21d[JPL];
    #pragma unroll
    for (int jj = 0; jj < JPL; jj++) {
        const int j = jj * 16 + jsel;
        float a = W1[j], b = W1[H + j], c = b1[j];
        float d = W2[2 * j], e = W2[2 * j + 1];
        w1ad[jj] = pk2(a, a);
        w1bd[jj] = pk2(b, b);
        b1d[jj]  = pk2(c, c);
        w20d[jj] = pk2(d, d);
        w21d[jj] = pk2(e, e);
    }
    float b2v0 = b2[0], b2v1 = b2[1];
    const ull b20p = pk2(b2v0, b2v0);
    const ull b21p = pk2(b2v1, b2v1);

    float2 ya = reinterpret_cast<const float2*>(y0)[r0];
    float2 yb = reinterpret_cast<const float2*>(y0)[r1];
    ull Y0 = pk2(ya.x, yb.x);   // y[0] of rows (A,B)
    ull Y1 = pk2(ya.y, yb.y);   // y[1] of rows (A,B)

    // ---- Euler integration: 4 j's/lane, zero LDS in the loop ------------
    #pragma unroll 1
    for (int s = 0; s < T_STEPS - 1; s++) {
        const float dt = dts[s];          // broadcast: 1 wavefront
        const ull dtp = pk2(dt, dt);
        ull acc0 = 0ull, acc1 = 0ull;     // {a0A,a0B}, {a1A,a1B}
        #pragma unroll
        for (int jj = 0; jj < JPL; jj++) {
            ull z = ffma2(Y1, w1bd[jj], ffma2(Y0, w1ad[jj], b1d[jj]));
            float2 zf = upk(z);
            ull hp = pk2(tanh_fast(zf.x), tanh_fast(zf.y));
            acc0 = ffma2(hp, w20d[jj], acc0);
            acc1 = ffma2(hp, w21d[jj], acc1);
        }
        acc0 = team_sum2(acc0);
        acc1 = team_sum2(acc1);
        Y0 = ffma2(dtp, fadd2(acc0, b20p), Y0);
        Y1 = ffma2(dtp, fadd2(acc1, b21p), Y1);
    }

    // ---- Classifier: 4 k's per lane (k = jsel + 16*i) --------------------
    ull acc[JPL];
    acc[0] = bc2d[jsel];
    acc[1] = bc2d[jsel + 16];
    acc[2] = bc2d[jsel + 32];
    acc[3] = bc2d[jsel + 48];

    #pragma unroll 1
    for (int j = 0; j < H; j++) {
        ulonglong2 c1 = cls1[j];                       // broadcast LDS.128
        ull hz = ffma2(Y1, c1.y, ffma2(Y0, c1.x, bc1d[j]));
        float2 hf = upk(hz);
        ull hp = pk2(fmaxf(hf.x, 0.f), fmaxf(hf.y, 0.f));
        const int base = (j * 16 + jsel) * 2;
        ulonglong2 wA = *reinterpret_cast<const ulonglong2*>(&wc2A[base]);
        ulonglong2 wB = *reinterpret_cast<const ulonglong2*>(&wc2B[base]);
        acc[0] = ffma2(hp, wA.x, acc[0]);
        acc[1] = ffma2(hp, wA.y, acc[1]);
        acc[2] = ffma2(hp, wB.x, acc[2]);
        acc[3] = ffma2(hp, wB.y, acc[3]);
    }

    ull o0 = 0ull, o1 = 0ull, o2 = 0ull;   // logit c packed {A,B}
    #pragma unroll
    for (int kk = 0; kk < JPL; kk++) {
        const int k = jsel + 16 * kk;
        float2 a = upk(acc[kk]);
        ull rp = pk2(fmaxf(a.x, 0.f), fmaxf(a.y, 0.f));
        o0 = ffma2(rp, wc3d[k * 3 + 0], o0);
        o1 = ffma2(rp, wc3d[k * 3 + 1], o1);
        o2 = ffma2(rp, wc3d[k * 3 + 2], o2);
    }
    o0 = team_sum2(o0);
    o1 = team_sum2(o1);
    o2 = team_sum2(o2);

    if (jsel == 0) {
        float2 a0 = upk(o0), a1 = upk(o1), a2 = upk(o2);
        out[r0 * 3 + 0] = a0.x + bc3s[0];
        out[r0 * 3 + 1] = a1.x + bc3s[1];
        out[r0 * 3 + 2] = a2.x + bc3s[2];
        out[r1 * 3 + 0] = a0.y + bc3s[0];
        out[r1 * 3 + 1] = a1.y + bc3s[1];
        out[r1 * 3 + 2] = a2.y + bc3s[2];
    }
}

extern "C" void kernel_launch(void* const* d_in, const int* in_sizes, int n_in,
                              void* d_out, int out_size) {
    const float* y0  = (const float*)d_in[0];
    const float* t   = (const float*)d_in[1];
    const float* W1  = (const float*)d_in[2];
    const float* b1  = (const float*)d_in[3];
    const float* W2  = (const float*)d_in[4];
    const float* b2  = (const float*)d_in[5];
    const float* Wc1 = (const float*)d_in[6];
    const float* bc1 = (const float*)d_in[7];
    const float* Wc2 = (const float*)d_in[8];
    const float* bc2 = (const float*)d_in[9];
    const float* Wc3 = (const float*)d_in[10];
    const float* bc3 = (const float*)d_in[11];
    float* out = (float*)d_out;

    const int nrows = in_sizes[0] / 2;
    // 4 rows per warp (2 teams x 2 packed rows); 28 warps per block.
    const int warps = (nrows + 3) / 4;
    const int blocks = (warps + (THREADS / 32) - 1) / (THREADS / 32); // 586 @ B=64K
    node_classifier_kernel<<<blocks, THREADS>>>(
        y0, t, W1, b1, W2, b2, Wc1, bc1, Wc2, bc2, Wc3, bc3, out, nrows);
}

// round 12
// speedup vs baseline: 2.8639x; 1.4314x over previous
#include <cuda_runtime.h>
#include <cuda_bf16.h>
#include <string.h>

// NeuralODEClassifier: B=65536 rows, 63 Euler steps of
// f(y)=tanh(y@W1+b1)@W2+b2, then classifier 2->64->relu->64->relu->3.
//
// R7 ncu: SHFL butterfly was the bottleneck (1.8cyc/SHFL, L1=76.5%).
// 8-lane teams cut SHFL 3x below the MUFU floor (111.6K cyc/SM); ODE
// weights live in registers (8 j's x 5 {w,w} pairs = 80 regs), zero LDS in
// the step loop. 128-thr blocks (16 pairs) give ~1% wave balance and let
// resident blocks overlap classifier LDS under integration MUFU.

#define T_STEPS 64
#define H 64
#define THREADS 128
#define JPL 8            // j's (and k's) per lane

typedef unsigned long long ull;

__device__ __forceinline__ ull pk2(float a, float b) {
    float2 f = make_float2(a, b);
    ull r; memcpy(&r, &f, 8); return r;
}
__device__ __forceinline__ float2 upk(ull v) {
    float2 f; memcpy(&f, &v, 8); return f;
}
__device__ __forceinline__ ull ffma2(ull a, ull b, ull c) {
    ull d;
    asm("fma.rn.f32x2 %0, %1, %2, %3;" : "=l"(d) : "l"(a), "l"(b), "l"(c));
    return d;
}
__device__ __forceinline__ ull fadd2(ull a, ull b) {
    ull d;
    asm("add.rn.f32x2 %0, %1, %2;" : "=l"(d) : "l"(a), "l"(b));
    return d;
}
__device__ __forceinline__ float tanh_fast(float x) {
    float r;
    asm("tanh.approx.f32 %0, %1;" : "=f"(r) : "f"(x));
    return r;
}
// allreduce a packed f32x2 over an 8-lane team (xor bits 0..2)
__device__ __forceinline__ ull team_sum2(ull v) {
    v = fadd2(v, __shfl_xor_sync(0xFFFFFFFFu, v, 1, 32));
    v = fadd2(v, __shfl_xor_sync(0xFFFFFFFFu, v, 2, 32));
    v = fadd2(v, __shfl_xor_sync(0xFFFFFFFFu, v, 4, 32));
    return v;
}

// Classifier Wc2 layout: wc2cls[(j*8+ksel)*10 + i] = {Wc2[j][ksel+8*i]}x2,
// i=0..7, 2-ull pad. 80B lane stride -> distinct banks, 80 % 16 == 0 keeps
// LDS.128 alignment.
#define WC2_SEG 10

__global__ __launch_bounds__(THREADS, 4)
void node_classifier_kernel(
    const float* __restrict__ y0,
    const float* __restrict__ t,
    const float* __restrict__ W1,  // (2,64)
    const float* __restrict__ b1,  // (64)
    const float* __restrict__ W2,  // (64,2)
    const float* __restrict__ b2,  // (2)
    const float* __restrict__ Wc1, // (2,64)
    const float* __restrict__ bc1, // (64)
    const float* __restrict__ Wc2, // (64,64)
    const float* __restrict__ bc2, // (64)
    const float* __restrict__ Wc3, // (64,3)
    const float* __restrict__ bc3, // (3)
    float* __restrict__ out,       // (B,3)
    int nrows)
{
    // ---- SMEM (classifier + dts; hot step loop touches only dts) --------
    __shared__ float dts[T_STEPS - 1];
    __shared__ __align__(16) ulonglong2 cls1[H];   // ({Wc1[0][j]}x2, {Wc1[1][j]}x2)
    __shared__ ull bc1d[H];                        // {bc1[j]}x2
    __shared__ __align__(16) ull wc2cls[H * 8 * WC2_SEG];  // 40 KB padded
    __shared__ ull bc2d[H];                        // {bc2[k]}x2
    __shared__ ull wc3d[H * 3];                    // {Wc3[k][c]}x2
    __shared__ float bc3s[3];

    const int tid = threadIdx.x;
    if (tid < H) {
        float p = Wc1[tid], q = Wc1[H + tid], r = bc1[tid], s = bc2[tid];
        cls1[tid] = make_ulonglong2(pk2(p, p), pk2(q, q));
        bc1d[tid] = pk2(r, r);
        bc2d[tid] = pk2(s, s);
    }
    if (tid < T_STEPS - 1) dts[tid] = t[tid + 1] - t[tid];
    for (int i = tid; i < H * H; i += THREADS) {
        int j = i >> 6, k = i & 63;
        int ksel = k & 7, kk = k >> 3;
        float w = Wc2[i];
        wc2cls[(j * 8 + ksel) * WC2_SEG + kk] = pk2(w, w);
    }
    for (int i = tid; i < H * 3; i += THREADS) {
        float w = Wc3[i];
        wc3d[i] = pk2(w, w);
    }
    if (tid < 3) bc3s[tid] = bc3[tid];
    __syncthreads();

    // ---- team / row mapping ---------------------------------------------
    const int lane = tid & 31;
    const int jsel = lane & 7;          // j/k subset within 8-lane team
    const int rowg = lane >> 3;         // 0..3: row-pair within warp
    const int gw = blockIdx.x * (THREADS / 32) + (tid >> 5);
    const int npairs = (nrows + 1) >> 1;
    int p = gw * 4 + rowg;
    if (p >= npairs) p = npairs - 1;    // clamp; surplus teams duplicate work
    const int r0 = 2 * p;
    const int r1 = (2 * p + 1 < nrows) ? 2 * p + 1 : r0;

    // ---- ODE weights for this lane's 8 j's -> duplicated register pairs -
    ull w1ad[JPL], w1bd[JPL], b1d[JPL], w20d[JPL], w21d[JPL];
    #pragma unroll
    for (int jj = 0; jj < JPL; jj++) {
        const int j = jj * 8 + jsel;
        float a = W1[j], b = W1[H + j], c = b1[j];
        float d = W2[2 * j], e = W2[2 * j + 1];
        w1ad[jj] = pk2(a, a);
        w1bd[jj] = pk2(b, b);
        b1d[jj]  = pk2(c, c);
        w20d[jj] = pk2(d, d);
        w21d[jj] = pk2(e, e);
    }
    float b2v0 = b2[0], b2v1 = b2[1];
    const ull b20p = pk2(b2v0, b2v0);
    const ull b21p = pk2(b2v1, b2v1);

    float2 ya = reinterpret_cast<const float2*>(y0)[r0];
    float2 yb = reinterpret_cast<const float2*>(y0)[r1];
    ull Y0 = pk2(ya.x, yb.x);   // y[0] of rows (A,B)
    ull Y1 = pk2(ya.y, yb.y);   // y[1] of rows (A,B)

    // ---- Euler integration: 8 j's/lane, zero weight LDS in the loop -----
    #pragma unroll 1
    for (int s = 0; s < T_STEPS - 1; s++) {
        const float dt = dts[s];          // broadcast: 1 wavefront
        const ull dtp = pk2(dt, dt);
        ull acc0 = 0ull, acc1 = 0ull;     // {a0A,a0B}, {a1A,a1B}
        #pragma unroll
        for (int jj = 0; jj < JPL; jj++) {
            ull z = ffma2(Y1, w1bd[jj], ffma2(Y0, w1ad[jj], b1d[jj]));
            float2 zf = upk(z);
            ull hp = pk2(tanh_fast(zf.x), tanh_fast(zf.y));
            acc0 = ffma2(hp, w20d[jj], acc0);
            acc1 = ffma2(hp, w21d[jj], acc1);
        }
        acc0 = team_sum2(acc0);
        acc1 = team_sum2(acc1);
        Y0 = ffma2(dtp, fadd2(acc0, b20p), Y0);
        Y1 = ffma2(dtp, fadd2(acc1, b21p), Y1);
    }

    // ---- Classifier: 8 k's per lane (k = jsel + 8*i) ---------------------
    ull acc[JPL];
    #pragma unroll
    for (int i = 0; i < JPL; i++) acc[i] = bc2d[jsel + 8 * i];

    #pragma unroll 1
    for (int j = 0; j < H; j++) {
        ulonglong2 c1 = cls1[j];                       // broadcast
        ull hz = ffma2(Y1, c1.y, ffma2(Y0, c1.x, bc1d[j]));
        float2 hf = upk(hz);
        ull hp = pk2(fmaxf(hf.x, 0.f), fmaxf(hf.y, 0.f));
        const ulonglong2* wrow = reinterpret_cast<const ulonglong2*>(
            &wc2cls[(j * 8 + jsel) * WC2_SEG]);
        #pragma unroll
        for (int q = 0; q < JPL / 2; q++) {
            ulonglong2 w2 = wrow[q];
            acc[2 * q]     = ffma2(hp, w2.x, acc[2 * q]);
            acc[2 * q + 1] = ffma2(hp, w2.y, acc[2 * q + 1]);
        }
    }

    ull o0 = 0ull, o1 = 0ull, o2 = 0ull;   // logit c packed {A,B}
    #pragma unroll
    for (int i = 0; i < JPL; i++) {
        const int k = jsel + 8 * i;
        float2 a = upk(acc[i]);
        ull rp = pk2(fmaxf(a.x, 0.f), fmaxf(a.y, 0.f));
        o0 = ffma2(rp, wc3d[k * 3 + 0], o0);
        o1 = ffma2(rp, wc3d[k * 3 + 1], o1);
        o2 = ffma2(rp, wc3d[k * 3 + 2], o2);
    }
    o0 = team_sum2(o0);
    o1 = team_sum2(o1);
    o2 = team_sum2(o2);

    if (jsel == 0) {
        float2 a0 = upk(o0), a1 = upk(o1), a2 = upk(o2);
        out[r0 * 3 + 0] = a0.x + bc3s[0];
        out[r0 * 3 + 1] = a1.x + bc3s[1];
        out[r0 * 3 + 2] = a2.x + bc3s[2];
        out[r1 * 3 + 0] = a0.y + bc3s[0];
        out[r1 * 3 + 1] = a1.y + bc3s[1];
        out[r1 * 3 + 2] = a2.y + bc3s[2];
    }
}

extern "C" void kernel_launch(void* const* d_in, const int* in_sizes, int n_in,
                              void* d_out, int out_size) {
    const float* y0  = (const float*)d_in[0];
    const float* t   = (const float*)d_in[1];
    const float* W1  = (const float*)d_in[2];
    const float* b1  = (const float*)d_in[3];
    const float* W2  = (const float*)d_in[4];
    const float* b2  = (const float*)d_in[5];
    const float* Wc1 = (const float*)d_in[6];
    const float* bc1 = (const float*)d_in[7];
    const float* Wc2 = (const float*)d_in[8];
    const float* bc2 = (const float*)d_in[9];
    const float* Wc3 = (const float*)d_in[10];
    const float* bc3 = (const float*)d_in[11];
    float* out = (float*)d_out;

    const int nrows = in_sizes[0] / 2;
    // 8 rows per warp (4 teams x 2 packed rows); 4 warps per block.
    const int warps = (nrows + 7) / 8;
    const int blocks = (warps + (THREADS / 32) - 1) / (THREADS / 32); // 2048 @ B=64K
    node_classifier_kernel<<<blocks, THREADS>>>(
        y0, t, W1, b1, W2, b2, Wc1, bc1, Wc2, bc2, Wc3, bc3, out, nrows);
}